// round 13
// baseline (speedup 1.0000x reference)
#include <cuda_runtime.h>
#include <cuda_bf16.h>
#include <math.h>

// Problem constants (fixed by the reference).
#define BATCH 4096
#define DIM   768
#define KNEG  60
#define NLOG  (KNEG + 1)      // 61 logits per row
#define CHUNKS 96             // DIM / 8 bf16-chunks of 16B
#define PER_LANE 3            // 96 / 32 lanes

typedef unsigned long long u64;

// 16-byte chunk of 8 bf16 values, viewed as 4x bf16x2 words.
struct alignas(16) BF8 { unsigned u[4]; };

// Scratch (no device allocation allowed -> __device__ globals).
__device__ BF8       g_items_bf16[BATCH * CHUNKS];   // 6.29 MB bf16 item table
__device__ float     g_row_loss[BATCH];
__device__ unsigned  g_done = 0;                     // last-block ticket

// ---- sm_103a packed-fp32 helpers (ptxas won't emit FFMA2 from plain C++) ----
__device__ __forceinline__ u64 pack_f32x2(float lo, float hi) {
    u64 r; asm("mov.b64 %0, {%1, %2};" : "=l"(r) : "f"(lo), "f"(hi)); return r;
}
// bf16x2 word (lo|hi) -> f32x2 pair: lo = w<<16, hi = w & 0xFFFF0000.
__device__ __forceinline__ u64 bf2_to_f32x2(unsigned w) {
    unsigned lo = w << 16, hi = w & 0xFFFF0000u;
    u64 r; asm("mov.b64 %0, {%1, %2};" : "=l"(r) : "r"(lo), "r"(hi)); return r;
}
__device__ __forceinline__ void ffma2(u64& d, u64 a, u64 b) {
    asm("fma.rn.f32x2 %0, %1, %2, %0;" : "+l"(d) : "l"(a), "l"(b));
}
__device__ __forceinline__ float hsum_f32x2(u64 a) {
    float lo, hi; asm("mov.b64 {%0, %1}, %2;" : "=f"(lo), "=f"(hi) : "l"(a));
    return lo + hi;
}
__device__ __forceinline__ unsigned pack_bf2(float x, float y) {
    __nv_bfloat162 t = __floats2bfloat162_rn(x, y);   // x -> low half
    return *reinterpret_cast<unsigned*>(&t);
}

// ---------------------------------------------------------------------------
// Kernel 1: convert the fp32 item table to bf16 (DRAM-bound, ~2.4us).
// ---------------------------------------------------------------------------
__global__ __launch_bounds__(256)
void convert_items_kernel(const float* __restrict__ items)
{
    const unsigned t = blockIdx.x * 256u + threadIdx.x;   // chunk id
    const float4* in = reinterpret_cast<const float4*>(items);
    float4 a = in[2u * t];
    float4 b = in[2u * t + 1u];
    BF8 o;
    o.u[0] = pack_bf2(a.x, a.y);
    o.u[1] = pack_bf2(a.z, a.w);
    o.u[2] = pack_bf2(b.x, b.y);
    o.u[3] = pack_bf2(b.z, b.w);
    g_items_bf16[t] = o;
}

// ---------------------------------------------------------------------------
// Kernel 2: one CTA per row. 8 warps; warp w computes logits {w, w+8, ...},
// two per iteration (6 outstanding LDG.128/lane). MACs use packed fp32x2
// FFMA (2 MACs/instr). The user row u[b] lives in SHARED memory (3 KB) and
// is re-read per iteration via LDS.128 -> frees ~24 regs/thread so 5 CTAs
// (40 warps) fit per SM instead of 4. Fused last-block mean.
// ---------------------------------------------------------------------------
__global__ __launch_bounds__(256, 5)
void u2i_row_kernel(const float* __restrict__ user,
                    const int*   __restrict__ negs,
                    float*       __restrict__ out)
{
    const int b    = blockIdx.x;
    const int tid  = threadIdx.x;
    const int warp = tid >> 5;
    const int lane = tid & 31;

    __shared__ float4 s_u[2 * CHUNKS];    // u[b] as 192 float4 (3 KB)
    __shared__ int    s_idx[NLOG];
    __shared__ float  s_logits[NLOG];
    __shared__ bool   s_last;
    __shared__ float  s_red[256];

    // Stage u[b] into smem (192 float4, one per thread t<192) and the
    // 61 logit indices (logit 0 = own positive row).
    if (tid < 2 * CHUNKS)
        s_u[tid] = reinterpret_cast<const float4*>(user + (size_t)b * DIM)[tid];
    if (tid == 0)          s_idx[0]   = b;
    else if (tid <= KNEG)  s_idx[tid] = negs[b * KNEG + (tid - 1)];
    __syncthreads();

    // 61 dot products, 2 per warp per iteration (j and j+8).
    for (int j = warp; j < NLOG; j += 16) {
        const int  j2   = j + 8;
        const bool has2 = (j2 < NLOG);
        const uint4* p1 = reinterpret_cast<const uint4*>(
            g_items_bf16 + (size_t)s_idx[j] * CHUNKS);
        const uint4* p2 = reinterpret_cast<const uint4*>(
            g_items_bf16 + (size_t)s_idx[has2 ? j2 : j] * CHUNKS);

        // Batch all 6 gathered loads first (MLP=6 per lane).
        uint4 r1[PER_LANE], r2[PER_LANE];
#pragma unroll
        for (int i = 0; i < PER_LANE; i++) {
            r1[i] = p1[lane + 32 * i];
            r2[i] = p2[lane + 32 * i];
        }

        u64 acc1 = 0ull, acc2 = 0ull;
#pragma unroll
        for (int i = 0; i < PER_LANE; i++) {
            const int c = lane + 32 * i;          // this lane's chunk id
            float4 A = s_u[2 * c];                // LDS.128 x2 (shared by
            float4 Bv = s_u[2 * c + 1];           //  both logits)
            u64 u0 = pack_f32x2(A.x,  A.y);
            u64 u1 = pack_f32x2(A.z,  A.w);
            u64 u2 = pack_f32x2(Bv.x, Bv.y);
            u64 u3 = pack_f32x2(Bv.z, Bv.w);
            ffma2(acc1, bf2_to_f32x2(r1[i].x), u0);
            ffma2(acc2, bf2_to_f32x2(r2[i].x), u0);
            ffma2(acc1, bf2_to_f32x2(r1[i].y), u1);
            ffma2(acc2, bf2_to_f32x2(r2[i].y), u1);
            ffma2(acc1, bf2_to_f32x2(r1[i].z), u2);
            ffma2(acc2, bf2_to_f32x2(r2[i].z), u2);
            ffma2(acc1, bf2_to_f32x2(r1[i].w), u3);
            ffma2(acc2, bf2_to_f32x2(r2[i].w), u3);
        }
        float a1 = hsum_f32x2(acc1);
        float a2 = hsum_f32x2(acc2);
#pragma unroll
        for (int off = 16; off; off >>= 1) {      // interleaved reduce chains
            a1 += __shfl_xor_sync(0xffffffffu, a1, off);
            a2 += __shfl_xor_sync(0xffffffffu, a2, off);
        }
        if (lane == 0) {
            s_logits[j] = a1;
            if (has2) s_logits[j2] = a2;
        }
    }
    __syncthreads();

    // Warp 0: 61-way logsumexp, loss = lse - logit[0]; then take a ticket.
    if (warp == 0) {
        const float NEG = -3.0e38f;              // expf underflows to 0
        float a = (lane      < NLOG) ? s_logits[lane]      : NEG;
        float c = (lane + 32 < NLOG) ? s_logits[lane + 32] : NEG;

        float m = fmaxf(a, c);
#pragma unroll
        for (int off = 16; off; off >>= 1)
            m = fmaxf(m, __shfl_xor_sync(0xffffffffu, m, off));

        float s = expf(a - m) + expf(c - m);
#pragma unroll
        for (int off = 16; off; off >>= 1)
            s += __shfl_xor_sync(0xffffffffu, s, off);

        if (lane == 0) {
            g_row_loss[b] = m + logf(s) - s_logits[0];
            __threadfence();
            s_last = (atomicAdd(&g_done, 1u) == BATCH - 1u);
        }
    }
    __syncthreads();

    // Last block to finish: deterministic fixed-order mean over all rows.
    if (s_last) {
        __threadfence();
        float s = 0.0f;
        for (int i = tid; i < BATCH; i += 256)
            s += __ldcg(&g_row_loss[i]);
        s_red[tid] = s;
        __syncthreads();
#pragma unroll
        for (int st = 128; st; st >>= 1) {
            if (tid < st) s_red[tid] += s_red[tid + st];
            __syncthreads();
        }
        if (tid == 0) {
            out[0] = s_red[0] * (1.0f / (float)BATCH);
            g_done = 0;                          // reset for next graph replay
        }
    }
}

// ---------------------------------------------------------------------------
// Harness entry point. Inputs per metadata order:
//   d_in[0] = user_emb     f32 (4096*768)
//   d_in[1] = pos_item_emb f32 (4096*768)
//   d_in[2] = neg_indices  i32 (4096*60)
// d_out = f32 scalar.  Graph-capturable: two launches, no sync, no alloc.
// ---------------------------------------------------------------------------
extern "C" void kernel_launch(void* const* d_in, const int* in_sizes, int n_in,
                              void* d_out, int out_size)
{
    (void)in_sizes; (void)n_in; (void)out_size;
    const float* user  = (const float*)d_in[0];
    const float* items = (const float*)d_in[1];
    const int*   negs  = (const int*)  d_in[2];
    float*       out   = (float*)      d_out;

    convert_items_kernel<<<(BATCH * CHUNKS) / 256, 256>>>(items);
    u2i_row_kernel<<<BATCH, 256>>>(user, negs, out);
}